// round 11
// baseline (speedup 1.0000x reference)
#include <cuda_runtime.h>
#include <cuda_bf16.h>
#include <math.h>
#include <stdint.h>

#define NB 128
#define NT 32
#define NIN 512
#define NH 512
#define NM 16
#define NWC 20
#define NR 4
#define NRW 80
#define NNIN 592
#define NIF 163
#define NIFP 192
#define CLIPV 20.0f
#define EPSF 1e-6f
#define DELTAF 5e-6f

#define NBLKS 148
#define NW (NBLKS * 8)   // 1184 warps

// ---------------- persistent state (device globals; allocation-free) ----------
__device__ float g_h[2][2][2][NB][NH];   // [parity][layer][cell][b][h]
__device__ float g_c[2][2][NB][NH];      // [layer][cell][b][h]
__device__ float g_inp[NB][NNIN];        // concat(out, read_vecs)
__device__ float g_ifc[NB][NIFP];        // iface projection result
__device__ float g_xpart[NT * 2048 * NB];// precomputed x@Wih partial, [t][n'][b]
__device__ float g_mem[2][NB][NM][NWC];
__device__ float g_link[2][NB][NM][NM];
__device__ float g_prec[2][NB][NM];
__device__ float g_rw[2][NB][NR][NM];
__device__ float g_ww[2][NB][NM];
__device__ float g_usage[2][NB][NM];
__device__ unsigned g_barCnt;

// ---------------- converted (bf16 hi/lo split, fragment-swizzled) weights ----
__device__ unsigned g_W00[128 * 64 * 256];   // l0 cell0: 2048 x (512x + 512h)
__device__ unsigned g_W01[128 * 69 * 256];   // l1 cell0: 2048 x 1104
__device__ unsigned g_W10[128 * 64 * 256];   // l0 cell1
__device__ unsigned g_W11[128 * 64 * 256];   // l1 cell1
__device__ unsigned g_Wif[2 * 12 * 32 * 256];// iface: 192(pad) x 512, per layer
__device__ unsigned g_Wo[32 * 37 * 256];     // out: 512 x 592
__device__ float g_bc[2 * 2 * 2048];         // gate-reordered biases [l][cell][n']

__device__ __forceinline__ float sigf(float x) { return 1.f / (1.f + expf(-x)); }
__device__ __forceinline__ float softplusf(float x) {
    return fmaxf(x, 0.f) + log1pf(expf(-fabsf(x)));
}
__device__ __forceinline__ float clipf(float x) {
    return fminf(fmaxf(x, -CLIPV), CLIPV);
}
__device__ __forceinline__ uint32_t packbf(float a, float b) {
    uint32_t r;
    asm("cvt.rn.bf16x2.f32 %0, %1, %2;" : "=r"(r) : "f"(b), "f"(a));
    return r;
}
__device__ __forceinline__ float bfhi(float x) {
    return __bfloat162float(__float2bfloat16_rn(x));
}
__device__ __forceinline__ void cvt_hilo(float x, float y, uint32_t& hi, uint32_t& lo) {
    uint32_t h = packbf(x, y);
    float hx = __uint_as_float(h << 16);
    float hy = __uint_as_float(h & 0xffff0000u);
    lo = packbf(x - hx, y - hy);
    hi = h;
}

// ---------------- init: zero all state --------------------------------------
__global__ void initk() {
    long i0 = blockIdx.x * (long)blockDim.x + threadIdx.x;
    long st = (long)gridDim.x * blockDim.x;
    if (i0 == 0) g_barCnt = 0u;
    for (long i = i0; i < 2L * 2 * 2 * NB * NH; i += st) ((float*)g_h)[i] = 0.f;
    for (long i = i0; i < 2L * 2 * NB * NH; i += st) ((float*)g_c)[i] = 0.f;
    for (long i = i0; i < (long)NB * NNIN; i += st) ((float*)g_inp)[i] = 0.f;
    for (long i = i0; i < 2L * NB * NM * NWC; i += st) ((float*)g_mem)[i] = 0.f;
    for (long i = i0; i < 2L * NB * NM * NM; i += st) ((float*)g_link)[i] = 0.f;
    for (long i = i0; i < 2L * NB * NM; i += st) {
        ((float*)g_prec)[i] = 0.f;
        ((float*)g_ww)[i] = 0.f;
        ((float*)g_usage)[i] = 0.f;
    }
    for (long i = i0; i < 2L * NB * NR * NM; i += st) ((float*)g_rw)[i] = 0.f;
}

// ---------------- fused weight conversion pre-pass (7 jobs, bf16 hi/lo) ------
__global__ void prepAll(
    const float* __restrict__ W_ih0, const float* __restrict__ W_hh0,
    const float* __restrict__ W_ih1, const float* __restrict__ W_hh1,
    const float* __restrict__ W_if,  const float* __restrict__ W_out,
    unsigned* pW00, unsigned* pW01, unsigned* pW10, unsigned* pW11,
    unsigned* pWif, unsigned* pWo)
{
    const float *W1, *W2;
    int ld1, K1, ld2, K2, gr, nReal, nPad;
    unsigned* dst;
    switch (blockIdx.y) {
        case 0: W1 = W_ih0; ld1 = NNIN; K1 = 512; W2 = W_hh0; ld2 = NH; K2 = 512;
                dst = pW00; gr = 1; nReal = 2048; nPad = 2048; break;
        case 1: W1 = W_ih0 + (size_t)4 * NH * NNIN; ld1 = NNIN; K1 = 592;
                W2 = W_hh0 + (size_t)4 * NH * NH; ld2 = NH; K2 = 512;
                dst = pW01; gr = 1; nReal = 2048; nPad = 2048; break;
        case 2: W1 = W_ih1; ld1 = NH; K1 = 512; W2 = W_hh1; ld2 = NH; K2 = 512;
                dst = pW10; gr = 1; nReal = 2048; nPad = 2048; break;
        case 3: W1 = W_ih1 + (size_t)4 * NH * NH; ld1 = NH; K1 = 512;
                W2 = W_hh1 + (size_t)4 * NH * NH; ld2 = NH; K2 = 512;
                dst = pW11; gr = 1; nReal = 2048; nPad = 2048; break;
        case 4: W1 = W_if; ld1 = NH; K1 = 512; W2 = W_if; ld2 = NH; K2 = 0;
                dst = pWif; gr = 0; nReal = NIF; nPad = 192; break;
        case 5: W1 = W_if + (size_t)NIF * NH; ld1 = NH; K1 = 512;
                W2 = W1; ld2 = NH; K2 = 0;
                dst = pWif + (size_t)12 * 32 * 256; gr = 0; nReal = NIF; nPad = 192; break;
        default: W1 = W_out; ld1 = NNIN; K1 = 592; W2 = W_out; ld2 = NNIN; K2 = 0;
                dst = pWo; gr = 0; nReal = 512; nPad = 512; break;
    }
    const int K16 = (K1 + K2) >> 4;
    int idx = blockIdx.x * blockDim.x + threadIdx.x;
    int total = (nPad >> 4) * K16 * 32;
    if (idx >= total) return;
    int lane = idx & 31;
    int k16 = (idx >> 5) % K16;
    int nfrag = (idx >> 5) / K16;
    int r0 = lane >> 2, c0 = lane & 3;
    uint4 hi, lo;
    unsigned* ph = (unsigned*)&hi;
    unsigned* pl = (unsigned*)&lo;
#pragma unroll
    for (int reg = 0; reg < 4; ++reg) {
        int r = nfrag * 16 + r0 + 8 * (reg & 1);
        int kb = k16 * 16 + 2 * c0 + 8 * (reg >> 1);
        int row;
        if (gr) { int j = r >> 2, g = r & 3; row = g * NH + j; }
        else row = r;
        float x0 = 0.f, x1 = 0.f;
        if (row < nReal) {
            x0 = (kb < K1) ? W1[(size_t)row * ld1 + kb]
                           : W2[(size_t)row * ld2 + (kb - K1)];
            x1 = (kb + 1 < K1) ? W1[(size_t)row * ld1 + kb + 1]
                               : W2[(size_t)row * ld2 + (kb + 1 - K1)];
        }
        float h0 = bfhi(x0), h1 = bfhi(x1);
        ph[reg] = packbf(h0, h1);
        pl[reg] = packbf(x0 - h0, x1 - h1);
    }
    ((uint4*)dst)[((size_t)(nfrag * K16 + k16) * 2 + 0) * 32 + lane] = hi;
    ((uint4*)dst)[((size_t)(nfrag * K16 + k16) * 2 + 1) * 32 + lane] = lo;
}

__global__ void prepbias(const float* bih0, const float* bhh0,
                         const float* bih1, const float* bhh1, float* bc)
{
    int i = blockIdx.x * blockDim.x + threadIdx.x;
    if (i >= 2 * 2 * 2048) return;
    int n = i & 2047;
    int cell = (i >> 11) & 1;
    int l = i >> 12;
    int j = n >> 2, g = n & 3;
    const float* bi = cell ? bih1 : bih0;
    const float* bh = cell ? bhh1 : bhh0;
    bc[i] = bi[(size_t)l * 4 * NH + g * NH + j] + bh[(size_t)l * 4 * NH + g * NH + j];
}

// ---------------- warp-level compensated bf16 GEMM core ----------------------
__device__ __forceinline__ void mma_bf16(float c[4], uint4 a, uint32_t b0, uint32_t b1) {
    asm volatile(
        "mma.sync.aligned.m16n8k16.row.col.f32.bf16.bf16.f32 "
        "{%0,%1,%2,%3}, {%4,%5,%6,%7}, {%8,%9}, {%0,%1,%2,%3};"
        : "+f"(c[0]), "+f"(c[1]), "+f"(c[2]), "+f"(c[3])
        : "r"(a.x), "r"(a.y), "r"(a.z), "r"(a.w), "r"(b0), "r"(b1));
}

__device__ __forceinline__ void gemmWarp(
    const float* __restrict__ A1, int sA1, int K1,
    const float* __restrict__ A2, int sA2,
    int nch, const uint4* __restrict__ Wp,
    int lane, int bcol, float acc[4])
{
    const int kb = 2 * (lane & 3);
    const float* rA1 = A1 + (size_t)bcol * sA1;
    const float* rA2 = A2 + (size_t)bcol * sA2 - K1;
    float2 B0[2], B1[2];
    uint4 WH[2], WL[2];
    acc[0] = acc[1] = acc[2] = acc[3] = 0.f;

    {
        int k = kb;
        const float* s = (k < K1) ? rA1 : rA2;
        B0[0] = __ldcg((const float2*)(s + k));
        B1[0] = __ldcg((const float2*)(s + k + 8));
    }
    WH[0] = Wp[0];
    WL[0] = Wp[32];
    if (nch > 1) {
        int k = 16 + kb;
        const float* s = (k < K1) ? rA1 : rA2;
        B0[1] = __ldcg((const float2*)(s + k));
        B1[1] = __ldcg((const float2*)(s + k + 8));
        WH[1] = Wp[64];
        WL[1] = Wp[96];
    }
    for (int ch = 0; ch < nch; ++ch) {
        const int s = ch & 1;
        uint32_t bh0, bl0, bh1, bl1;
        cvt_hilo(B0[s].x, B0[s].y, bh0, bl0);
        cvt_hilo(B1[s].x, B1[s].y, bh1, bl1);
        mma_bf16(acc, WH[s], bh0, bh1);
        mma_bf16(acc, WL[s], bh0, bh1);
        mma_bf16(acc, WH[s], bl0, bl1);
        if (ch + 2 < nch) {
            int k = (ch + 2) * 16 + kb;
            const float* sp = (k < K1) ? rA1 : rA2;
            B0[s] = __ldcg((const float2*)(sp + k));
            B1[s] = __ldcg((const float2*)(sp + k + 8));
            WH[s] = Wp[(size_t)(ch + 2) * 64];
            WL[s] = Wp[(size_t)(ch + 2) * 64 + 32];
        }
    }
}

// cell job: 16 n' (1 nfrag = 4 gate quads) x 8 batch; LSTM epilogue
__device__ __forceinline__ void cellJob(
    int job, int lane, float* slab,
    const float* A1, int sA1, int K1, const float* A2, int sA2,
    int nch, const unsigned* W, int kstr, int chOff,
    const float* bias, float* cio, float* hout, float* clipOut,
    const float* extra)
{
    int nfrag = job >> 4, tb = job & 15;
    int bcol = tb * 8 + (lane >> 2);
    const uint4* Wp = (const uint4*)W + ((size_t)nfrag * kstr + chOff) * 64 + lane;
    float acc[4];
    gemmWarp(A1, sA1, K1, A2, sA2, nch, Wp, lane, bcol, acc);
    int r = lane >> 2, cc = 2 * (lane & 3);
    slab[r * 9 + cc] = acc[0];
    slab[r * 9 + cc + 1] = acc[1];
    slab[(r + 8) * 9 + cc] = acc[2];
    slab[(r + 8) * 9 + cc + 1] = acc[3];
    __syncwarp();
    int j = lane >> 3, bl = lane & 7;
    int b = tb * 8 + bl;
    int jg = nfrag * 4 + j;
    int nb = nfrag * 16 + j * 4;
    float e0 = 0.f, e1 = 0.f, e2 = 0.f, e3 = 0.f;
    if (extra) {
        const float* ep = extra + (size_t)nb * NB + b;
        e0 = ep[0]; e1 = ep[NB]; e2 = ep[2 * NB]; e3 = ep[3 * NB];
    }
    float gi = slab[(j * 4 + 0) * 9 + bl] + bias[nb + 0] + e0;
    float gf = slab[(j * 4 + 1) * 9 + bl] + bias[nb + 1] + e1;
    float gg = slab[(j * 4 + 2) * 9 + bl] + bias[nb + 2] + e2;
    float go = slab[(j * 4 + 3) * 9 + bl] + bias[nb + 3] + e3;
    float cold = cio[(size_t)b * NH + jg];
    float cn = sigf(gf) * cold + sigf(gi) * tanhf(gg);
    float hn = sigf(go) * tanhf(cn);
    cio[(size_t)b * NH + jg] = cn;
    hout[(size_t)b * NH + jg] = hn;
    if (clipOut) clipOut[(size_t)b * NNIN + jg] = clipf(hn);
    __syncwarp();
}

// linear job: 16 n x 8 batch, bias + row guard
__device__ __forceinline__ void linJob(
    int job, int lane, float* slab,
    const float* A1, int sA1, int K1, const float* A2, int sA2,
    int nch, const unsigned* W, int kstr,
    const float* bias, int nReal, float* out, int rowStride)
{
    int nfrag = job >> 4, tb = job & 15;
    int bcol = tb * 8 + (lane >> 2);
    const uint4* Wp = (const uint4*)W + (size_t)nfrag * kstr * 64 + lane;
    float acc[4];
    gemmWarp(A1, sA1, K1, A2, sA2, nch, Wp, lane, bcol, acc);
    int r = lane >> 2, cc = 2 * (lane & 3);
    slab[r * 9 + cc] = acc[0];
    slab[r * 9 + cc + 1] = acc[1];
    slab[(r + 8) * 9 + cc] = acc[2];
    slab[(r + 8) * 9 + cc + 1] = acc[3];
    __syncwarp();
#pragma unroll
    for (int i = 0; i < 4; ++i) {
        int idx = i * 32 + lane;
        int n = idx >> 3, bl = idx & 7;
        int ng = nfrag * 16 + n;
        if (ng < nReal)
            out[(size_t)(tb * 8 + bl) * rowStride + ng] = slab[n * 9 + bl] + bias[ng];
    }
    __syncwarp();
}

// ---------------- warp-level DNC memory step ---------------------------------
__device__ void memstepWarp(int lane, int b,
    const float* ifcg, float* memg, float* linkg, float* precg,
    float* rwg, float* wwg, float* usg, float* inp, float* ws)
{
    const int RS = 80, WK = 84, WS = 104, ER = 105, WV = 125,
              FG = 145, AG = 149, WG = 150, RM = 151;
    float* ifc = ws;          // 164
    float* sm  = ws + 164;    // 320
    float* sl  = ws + 484;    // 256
    float* sp  = ws + 740;    // 16
    float* srw = ws + 756;    // 64
    float* sww = ws + 820;    // 16
    float* sus = ws + 836;    // 16
    float* wcw = ws + 852;    // 16
    float* alo = ws + 868;    // 16
    float* rcw = ws + 884;    // 64
    float* fwd = ws + 948;    // 64
    float* bwd = ws + 1012;   // 64

    for (int i = lane; i < NIF; i += 32) ifc[i] = __ldcg(ifcg + (size_t)b * NIFP + i);
    for (int i = lane; i < 320; i += 32) sm[i] = memg[b * 320 + i];
    for (int i = lane; i < 256; i += 32) sl[i] = linkg[b * 256 + i];
    if (lane < 16) {
        sp[lane] = precg[b * 16 + lane];
        sww[lane] = wwg[b * 16 + lane];
        sus[lane] = usg[b * 16 + lane];
    }
    for (int i = lane; i < 64; i += 32) srw[i] = rwg[b * 64 + i];
    __syncwarp();

    if (lane < 16) {
        float uu = sus[lane] + (1.f - sus[lane]) * sww[lane];
        float psi = 1.f;
#pragma unroll
        for (int r = 0; r < NR; ++r) psi *= 1.f - sigf(ifc[FG + r]) * srw[r * 16 + lane];
        sus[lane] = uu * psi;
        float kn2 = 0.f, dot = 0.f, mn2 = 0.f;
#pragma unroll
        for (int w = 0; w < NWC; ++w) {
            float kv = tanhf(ifc[WK + w]);
            float mv = sm[lane * NWC + w];
            kn2 = fmaf(kv, kv, kn2);
            mn2 = fmaf(mv, mv, mn2);
            dot = fmaf(kv, mv, dot);
        }
        float v = dot / ((sqrtf(kn2) + EPSF) * (sqrtf(mn2) + EPSF));
        v *= softplusf(ifc[WS]);
        float mx = v;
#pragma unroll
        for (int o = 8; o; o >>= 1) mx = fmaxf(mx, __shfl_xor_sync(0xffffu, mx, o, 16));
        float e = expf(v - mx);
        float s = e;
#pragma unroll
        for (int o = 8; o; o >>= 1) s += __shfl_xor_sync(0xffffu, s, o, 16);
        wcw[lane] = e / s;
    }
    __syncwarp();
    if (lane == 0) {
        float u[16]; int idx[16];
        for (int m = 0; m < 16; ++m) { u[m] = DELTAF + (1.f - DELTAF) * sus[m]; idx[m] = m; }
        for (int i = 1; i < 16; ++i) {
            float kv = u[i]; int ki = idx[i]; int j = i;
            while (j > 0 && u[j - 1] > kv) { u[j] = u[j - 1]; idx[j] = idx[j - 1]; --j; }
            u[j] = kv; idx[j] = ki;
        }
        float prod = 1.f;
        for (int j = 0; j < 16; ++j) { alo[idx[j]] = (1.f - u[j]) * prod; prod *= u[j]; }
    }
    __syncwarp();
    if (lane < 16) {
        float ag = sigf(ifc[AG]), wg = sigf(ifc[WG]);
        sww[lane] = wg * (ag * alo[lane] + (1.f - ag) * wcw[lane]);
    }
    __syncwarp();
    for (int i = lane; i < 320; i += 32) {
        int m = i / NWC, w = i % NWC;
        float e = sigf(ifc[ER + w]);
        float v = tanhf(ifc[WV + w]);
        sm[i] = sm[i] * (1.f - sww[m] * e) + sww[m] * v;
    }
    __syncwarp();
    for (int i = lane; i < 256; i += 32) {
        int ii = i >> 4, jj = i & 15;
        sl[i] = (ii == jj) ? 0.f
                           : (1.f - sww[ii] - sww[jj]) * sl[i] + sww[ii] * sp[jj];
    }
    __syncwarp();
    if (lane < 16) {
        float s = 0.f;
#pragma unroll
        for (int m = 0; m < 16; ++m) s += sww[m];
        sp[lane] = (1.f - s) * sp[lane] + sww[lane];
    }
    __syncwarp();
#pragma unroll
    for (int it = 0; it < 2; ++it) {
        int i = it * 32 + lane;
        int r = i >> 4, m = i & 15;
        float kn2 = 0.f, dot = 0.f, mn2 = 0.f;
#pragma unroll
        for (int w = 0; w < NWC; ++w) {
            float kv = tanhf(ifc[r * NWC + w]);
            float mv = sm[m * NWC + w];
            kn2 = fmaf(kv, kv, kn2);
            mn2 = fmaf(mv, mv, mn2);
            dot = fmaf(kv, mv, dot);
        }
        float v = dot / ((sqrtf(kn2) + EPSF) * (sqrtf(mn2) + EPSF));
        v *= softplusf(ifc[RS + r]);
        float mx = v;
#pragma unroll
        for (int o = 8; o; o >>= 1) mx = fmaxf(mx, __shfl_xor_sync(0xffffffffu, mx, o, 16));
        float e = expf(v - mx);
        float s = e;
#pragma unroll
        for (int o = 8; o; o >>= 1) s += __shfl_xor_sync(0xffffffffu, s, o, 16);
        rcw[i] = e / s;
    }
    __syncwarp();
#pragma unroll
    for (int it = 0; it < 2; ++it) {
        int i = it * 32 + lane;
        int r = i >> 4, q = i & 15;
        float f = 0.f, bb = 0.f;
#pragma unroll
        for (int j = 0; j < 16; ++j) {
            f = fmaf(sl[q * 16 + j], srw[r * 16 + j], f);
            bb = fmaf(srw[r * 16 + j], sl[j * 16 + q], bb);
        }
        fwd[i] = f;
        bwd[i] = bb;
    }
    __syncwarp();
#pragma unroll
    for (int it = 0; it < 2; ++it) {
        int i = it * 32 + lane;
        int r = i >> 4;
        float e0 = ifc[RM + r * 3 + 0], e1 = ifc[RM + r * 3 + 1], e2 = ifc[RM + r * 3 + 2];
        float mx = fmaxf(e0, fmaxf(e1, e2));
        float x0 = expf(e0 - mx), x1 = expf(e1 - mx), x2 = expf(e2 - mx);
        float inv = 1.f / (x0 + x1 + x2);
        srw[i] = (x0 * bwd[i] + x1 * fwd[i] + x2 * rcw[i]) * inv;
    }
    __syncwarp();
    for (int i = lane; i < NRW; i += 32) {
        int r = i / NWC, w = i % NWC;
        float s = 0.f;
#pragma unroll
        for (int m = 0; m < 16; ++m) s = fmaf(srw[r * 16 + m], sm[m * NWC + w], s);
        inp[(size_t)b * NNIN + NIN + i] = s;
    }
    for (int i = lane; i < 320; i += 32) memg[b * 320 + i] = sm[i];
    for (int i = lane; i < 256; i += 32) linkg[b * 256 + i] = sl[i];
    if (lane < 16) {
        precg[b * 16 + lane] = sp[lane];
        wwg[b * 16 + lane] = sww[lane];
        usg[b * 16 + lane] = sus[lane];
    }
    for (int i = lane; i < 64; i += 32) rwg[b * 64 + i] = srw[i];
    __syncwarp();
}

// ---------------- software grid barrier --------------------------------------
__device__ __forceinline__ void gbar(unsigned& target) {
    __threadfence();
    __syncthreads();
    if (threadIdx.x == 0) {
        atomicAdd(&g_barCnt, 1u);
        while (atomicAdd(&g_barCnt, 0u) < target) { }
        __threadfence();
    }
    __syncthreads();
    target += NBLKS;
}

// ---------------- the fused persistent recurrence kernel ---------------------
__global__ __launch_bounds__(256) void fused(
    const float* __restrict__ b_if, const float* __restrict__ b_out,
    float* __restrict__ y)
{
    __shared__ float sh[8 * 1088];
    const int wid = blockIdx.x * 8 + (threadIdx.x >> 5);
    const int lane = threadIdx.x & 31;
    float* slab = sh + (threadIdx.x >> 5) * 1088;
    float* pinp = &g_inp[0][0];
    unsigned target = NBLKS;

    for (int t = 0; t < NT; ++t) {
        const int p = t & 1;
        // S1: cell0-l0 (+ outproj of t-1 on spare jobs)
        for (int job = wid; job < 2560; job += NW) {
            if (job < 2048)
                cellJob(job, lane, slab,
                        &g_h[p][0][0][0][0], NH, 512, &g_h[p][0][0][0][0], NH,
                        32, g_W00, 64, 32,
                        g_bc, &g_c[0][0][0][0], &g_h[p ^ 1][0][0][0][0], nullptr,
                        g_xpart + (size_t)t * 2048 * NB);
            else if (t > 0)
                linJob(job - 2048, lane, slab,
                       pinp, NNIN, 592, pinp, NNIN,
                       37, g_Wo, 37,
                       b_out, 512, y + (size_t)(t - 1) * NIN, NT * NIN);
        }
        gbar(target);
        // S2: cell1-l0
        for (int job = wid; job < 2048; job += NW)
            cellJob(job, lane, slab,
                    &g_h[p ^ 1][0][0][0][0], NH, 512, &g_h[p][0][1][0][0], NH,
                    64, g_W10, 64, 0,
                    g_bc + 2048, &g_c[0][1][0][0], &g_h[p ^ 1][0][1][0][0], pinp,
                    nullptr);
        gbar(target);
        // S3: iface l0
        if (wid < 192)
            linJob(wid, lane, slab,
                   pinp, NNIN, 512, pinp, NNIN,
                   32, g_Wif, 32,
                   b_if, NIF, &g_ifc[0][0], NIFP);
        gbar(target);
        // S4: memstep l0
        if (wid < NB)
            memstepWarp(lane, wid, &g_ifc[0][0],
                        &g_mem[0][0][0][0], &g_link[0][0][0][0], &g_prec[0][0][0],
                        &g_rw[0][0][0][0], &g_ww[0][0][0], &g_usage[0][0][0],
                        pinp, slab);
        gbar(target);
        // S5: cell0-l1
        for (int job = wid; job < 2048; job += NW)
            cellJob(job, lane, slab,
                    pinp, NNIN, 592, &g_h[p][1][0][0][0], NH,
                    69, g_W01, 69, 0,
                    g_bc + 2 * 2048, &g_c[1][0][0][0], &g_h[p ^ 1][1][0][0][0],
                    nullptr, nullptr);
        gbar(target);
        // S6: cell1-l1
        for (int job = wid; job < 2048; job += NW)
            cellJob(job, lane, slab,
                    &g_h[p ^ 1][1][0][0][0], NH, 512, &g_h[p][1][1][0][0], NH,
                    64, g_W11, 64, 0,
                    g_bc + 3 * 2048, &g_c[1][1][0][0], &g_h[p ^ 1][1][1][0][0],
                    pinp, nullptr);
        gbar(target);
        // S7: iface l1
        if (wid < 192)
            linJob(wid, lane, slab,
                   pinp, NNIN, 512, pinp, NNIN,
                   32, g_Wif + 12 * 32 * 256, 32,
                   b_if + NIF, NIF, &g_ifc[0][0], NIFP);
        gbar(target);
        // S8: memstep l1
        if (wid < NB)
            memstepWarp(lane, wid, &g_ifc[0][0],
                        &g_mem[1][0][0][0], &g_link[1][0][0][0], &g_prec[1][0][0],
                        &g_rw[1][0][0][0], &g_ww[1][0][0], &g_usage[1][0][0],
                        pinp, slab);
        gbar(target);
    }
    // final output projection (t = NT-1)
    for (int job = wid; job < 512; job += NW)
        linJob(job, lane, slab,
               pinp, NNIN, 592, pinp, NNIN,
               37, g_Wo, 37,
               b_out, 512, y + (size_t)(NT - 1) * NIN, NT * NIN);
}

// ---------------- x-precompute (one-time, fully parallel) --------------------
// 16384 warp-jobs: nfrag (128) x batch-quad tq (128, 32 rows each) -> FULL
// coverage of 2048 n' x 4096 (b*NT+t) rows. 4 B-fragments share each W load.
__global__ __launch_bounds__(128) void xprep(
    const float* __restrict__ x, const unsigned* __restrict__ W,
    float* __restrict__ xpart)
{
    __shared__ float sbuf[4][16 * 9];
    const int lane = threadIdx.x & 31, warp = threadIdx.x >> 5;
    const int job = blockIdx.x * 4 + warp;        // 0..16383
    const int nfrag = job & 127;                  // 0..127 -> n' 16-row frag
    const int tq = job >> 7;                      // 0..127 -> rows tq*32..+31
    const uint4* Wp = (const uint4*)W + (size_t)nfrag * 64 * 64 + lane;
    const int kb = 2 * (lane & 3);
    const float* rA[4];
#pragma unroll
    for (int f = 0; f < 4; ++f)
        rA[f] = x + (size_t)(tq * 32 + f * 8 + (lane >> 2)) * NIN;
    float acc[4][4];
#pragma unroll
    for (int f = 0; f < 4; ++f)
        acc[f][0] = acc[f][1] = acc[f][2] = acc[f][3] = 0.f;
    for (int ch = 0; ch < 32; ++ch) {
        uint4 WH = Wp[(size_t)ch * 64];
        uint4 WL = Wp[(size_t)ch * 64 + 32];
        int k = ch * 16 + kb;
#pragma unroll
        for (int f = 0; f < 4; ++f) {
            float2 v0 = *(const float2*)(rA[f] + k);
            float2 v1 = *(const float2*)(rA[f] + k + 8);
            uint32_t bh0, bl0, bh1, bl1;
            cvt_hilo(v0.x, v0.y, bh0, bl0);
            cvt_hilo(v1.x, v1.y, bh1, bl1);
            mma_bf16(acc[f], WH, bh0, bh1);
            mma_bf16(acc[f], WL, bh0, bh1);
            mma_bf16(acc[f], WH, bl0, bl1);
        }
    }
    float* slab = sbuf[warp];
    int r = lane >> 2, cc = 2 * (lane & 3);
#pragma unroll
    for (int f = 0; f < 4; ++f) {
        __syncwarp();
        slab[r * 9 + cc] = acc[f][0];
        slab[r * 9 + cc + 1] = acc[f][1];
        slab[(r + 8) * 9 + cc] = acc[f][2];
        slab[(r + 8) * 9 + cc + 1] = acc[f][3];
        __syncwarp();
#pragma unroll
        for (int i = 0; i < 4; ++i) {
            int idx = i * 32 + lane;
            int n = idx >> 3, bl = idx & 7;
            int ng = nfrag * 16 + n;
            int bg = tq * 32 + f * 8 + bl;        // 0..4095 = b*NT + t
            int t = bg & (NT - 1);
            int bi = bg >> 5;                     // 0..127
            xpart[((size_t)t * 2048 + ng) * NB + bi] = slab[n * 9 + bl];
        }
    }
}

// ---------------- host driver ------------------------------------------------
extern "C" void kernel_launch(void* const* d_in, const int* in_sizes, int n_in,
                              void* d_out, int out_size)
{
    const float* x      = (const float*)d_in[0];
    const float* W_ih0  = (const float*)d_in[1];
    const float* W_hh0  = (const float*)d_in[2];
    const float* b_ih0  = (const float*)d_in[3];
    const float* b_hh0  = (const float*)d_in[4];
    const float* W_ih1  = (const float*)d_in[5];
    const float* W_hh1  = (const float*)d_in[6];
    const float* b_ih1  = (const float*)d_in[7];
    const float* b_hh1  = (const float*)d_in[8];
    const float* W_if   = (const float*)d_in[9];
    const float* b_if   = (const float*)d_in[10];
    const float* W_out  = (const float*)d_in[11];
    const float* b_out  = (const float*)d_in[12];
    float* y = (float*)d_out;

    float *pxp, *pbc;
    unsigned *pW00, *pW01, *pW10, *pW11, *pWif, *pWo;
    cudaGetSymbolAddress((void**)&pxp,  g_xpart);
    cudaGetSymbolAddress((void**)&pW00, g_W00);
    cudaGetSymbolAddress((void**)&pW01, g_W01);
    cudaGetSymbolAddress((void**)&pW10, g_W10);
    cudaGetSymbolAddress((void**)&pW11, g_W11);
    cudaGetSymbolAddress((void**)&pWif, g_Wif);
    cudaGetSymbolAddress((void**)&pWo,  g_Wo);
    cudaGetSymbolAddress((void**)&pbc,  g_bc);

    initk<<<512, 256>>>();
    prepAll<<<dim3(1104, 7), 256>>>(W_ih0, W_hh0, W_ih1, W_hh1, W_if,
                                    W_out, pW00, pW01, pW10, pW11, pWif, pWo);
    prepbias<<<(2 * 2 * 2048 + 255) / 256, 256>>>(b_ih0, b_hh0, b_ih1, b_hh1, pbc);
    xprep<<<4096, 128>>>(x, pW00, pxp);
    fused<<<NBLKS, 256>>>(b_if, b_out, y);
}

// round 15
// speedup vs baseline: 1.2394x; 1.2394x over previous
#include <cuda_runtime.h>
#include <cuda_bf16.h>
#include <math.h>
#include <stdint.h>

#define NB 128
#define NT 32
#define NIN 512
#define NH 512
#define NM 16
#define NWC 20
#define NR 4
#define NRW 80
#define NNIN 592
#define NIF 163
#define CLIPV 20.0f
#define EPSF 1e-6f
#define DELTAF 5e-6f

// ---------------- persistent state (device globals; allocation-free) ----------
__device__ float g_h[2][2][2][NB][NH];   // [parity][layer][cell][b][h]
__device__ float g_c[2][2][NB][NH];      // [layer][cell][b][h]
__device__ float g_inp[NB][NNIN];        // concat(out, read_vecs)
__device__ float g_xpart[NT * 2048 * NB];// precomputed x@Wih partial, [t][n'][b]
__device__ float g_mem[2][NB][NM][NWC];
__device__ float g_link[2][NB][NM][NM];
__device__ float g_prec[2][NB][NM];
__device__ float g_rw[2][NB][NR][NM];
__device__ float g_ww[2][NB][NM];
__device__ float g_usage[2][NB][NM];

// ---------------- converted (bf16 hi/lo split, fragment-swizzled) weights ----
// layout: [nfrag][k16][hl 2][lane 32][4 u32]
__device__ unsigned g_W00[128 * 64 * 256];   // l0 cell0: 2048 x (512x + 512h)
__device__ unsigned g_W01[128 * 69 * 256];   // l1 cell0: 2048 x 1104
__device__ unsigned g_W10[128 * 64 * 256];   // l0 cell1
__device__ unsigned g_W11[128 * 64 * 256];   // l1 cell1
__device__ unsigned g_Wo[32 * 37 * 256];     // out: 512 x 592
__device__ float g_bc[2 * 2 * 2048];         // gate-reordered biases [l][cell][n']

__device__ __forceinline__ float sigf(float x) { return 1.f / (1.f + expf(-x)); }
__device__ __forceinline__ float softplusf(float x) {
    return fmaxf(x, 0.f) + log1pf(expf(-fabsf(x)));
}
__device__ __forceinline__ float clipf(float x) {
    return fminf(fmaxf(x, -CLIPV), CLIPV);
}
__device__ __forceinline__ uint32_t packbf(float a, float b) {
    uint32_t r;
    asm("cvt.rn.bf16x2.f32 %0, %1, %2;" : "=r"(r) : "f"(b), "f"(a));
    return r;
}
__device__ __forceinline__ float bfhi(float x) {
    return __bfloat162float(__float2bfloat16_rn(x));
}
__device__ __forceinline__ void cvt_hilo(float x, float y, uint32_t& hi, uint32_t& lo) {
    uint32_t h = packbf(x, y);
    float hx = __uint_as_float(h << 16);
    float hy = __uint_as_float(h & 0xffff0000u);
    lo = packbf(x - hx, y - hy);
    hi = h;
}

// ---------------- init: zero all state --------------------------------------
__global__ void initk() {
    long i0 = blockIdx.x * (long)blockDim.x + threadIdx.x;
    long st = (long)gridDim.x * blockDim.x;
    for (long i = i0; i < 2L * 2 * 2 * NB * NH; i += st) ((float*)g_h)[i] = 0.f;
    for (long i = i0; i < 2L * 2 * NB * NH; i += st) ((float*)g_c)[i] = 0.f;
    for (long i = i0; i < (long)NB * NNIN; i += st) ((float*)g_inp)[i] = 0.f;
    for (long i = i0; i < 2L * NB * NM * NWC; i += st) ((float*)g_mem)[i] = 0.f;
    for (long i = i0; i < 2L * NB * NM * NM; i += st) ((float*)g_link)[i] = 0.f;
    for (long i = i0; i < 2L * NB * NM; i += st) {
        ((float*)g_prec)[i] = 0.f;
        ((float*)g_ww)[i] = 0.f;
        ((float*)g_usage)[i] = 0.f;
    }
    for (long i = i0; i < 2L * NB * NR * NM; i += st) ((float*)g_rw)[i] = 0.f;
}

// ---------------- fused weight conversion pre-pass (5 jobs, bf16 hi/lo) ------
__global__ void prepAll(
    const float* __restrict__ W_ih0, const float* __restrict__ W_hh0,
    const float* __restrict__ W_ih1, const float* __restrict__ W_hh1,
    const float* __restrict__ W_out,
    unsigned* pW00, unsigned* pW01, unsigned* pW10, unsigned* pW11,
    unsigned* pWo)
{
    const float *W1, *W2;
    int ld1, K1, ld2, K2, gr, nReal, nPad;
    unsigned* dst;
    switch (blockIdx.y) {
        case 0: W1 = W_ih0; ld1 = NNIN; K1 = 512; W2 = W_hh0; ld2 = NH; K2 = 512;
                dst = pW00; gr = 1; nReal = 2048; nPad = 2048; break;
        case 1: W1 = W_ih0 + (size_t)4 * NH * NNIN; ld1 = NNIN; K1 = 592;
                W2 = W_hh0 + (size_t)4 * NH * NH; ld2 = NH; K2 = 512;
                dst = pW01; gr = 1; nReal = 2048; nPad = 2048; break;
        case 2: W1 = W_ih1; ld1 = NH; K1 = 512; W2 = W_hh1; ld2 = NH; K2 = 512;
                dst = pW10; gr = 1; nReal = 2048; nPad = 2048; break;
        case 3: W1 = W_ih1 + (size_t)4 * NH * NH; ld1 = NH; K1 = 512;
                W2 = W_hh1 + (size_t)4 * NH * NH; ld2 = NH; K2 = 512;
                dst = pW11; gr = 1; nReal = 2048; nPad = 2048; break;
        default: W1 = W_out; ld1 = NNIN; K1 = 592; W2 = W_out; ld2 = NNIN; K2 = 0;
                dst = pWo; gr = 0; nReal = 512; nPad = 512; break;
    }
    const int K16 = (K1 + K2) >> 4;
    int idx = blockIdx.x * blockDim.x + threadIdx.x;
    int total = (nPad >> 4) * K16 * 32;
    if (idx >= total) return;
    int lane = idx & 31;
    int k16 = (idx >> 5) % K16;
    int nfrag = (idx >> 5) / K16;
    int r0 = lane >> 2, c0 = lane & 3;
    uint4 hi, lo;
    unsigned* ph = (unsigned*)&hi;
    unsigned* pl = (unsigned*)&lo;
#pragma unroll
    for (int reg = 0; reg < 4; ++reg) {
        int r = nfrag * 16 + r0 + 8 * (reg & 1);
        int kb = k16 * 16 + 2 * c0 + 8 * (reg >> 1);
        int row;
        if (gr) { int j = r >> 2, g = r & 3; row = g * NH + j; }
        else row = r;
        float x0 = 0.f, x1 = 0.f;
        if (row < nReal) {
            x0 = (kb < K1) ? W1[(size_t)row * ld1 + kb]
                           : W2[(size_t)row * ld2 + (kb - K1)];
            x1 = (kb + 1 < K1) ? W1[(size_t)row * ld1 + kb + 1]
                               : W2[(size_t)row * ld2 + (kb + 1 - K1)];
        }
        float h0 = bfhi(x0), h1 = bfhi(x1);
        ph[reg] = packbf(h0, h1);
        pl[reg] = packbf(x0 - h0, x1 - h1);
    }
    ((uint4*)dst)[((size_t)(nfrag * K16 + k16) * 2 + 0) * 32 + lane] = hi;
    ((uint4*)dst)[((size_t)(nfrag * K16 + k16) * 2 + 1) * 32 + lane] = lo;
}

__global__ void prepbias(const float* bih0, const float* bhh0,
                         const float* bih1, const float* bhh1, float* bc)
{
    int i = blockIdx.x * blockDim.x + threadIdx.x;
    if (i >= 2 * 2 * 2048) return;
    int n = i & 2047;
    int cell = (i >> 11) & 1;
    int l = i >> 12;
    int j = n >> 2, g = n & 3;
    const float* bi = cell ? bih1 : bih0;
    const float* bh = cell ? bhh1 : bhh0;
    bc[i] = bi[(size_t)l * 4 * NH + g * NH + j] + bh[(size_t)l * 4 * NH + g * NH + j];
}

// ---------------- compensated bf16 tensor-core GEMM (register-direct B) ------
__device__ __forceinline__ void mma_bf16(float c[4], uint4 a, uint32_t b0, uint32_t b1) {
    asm volatile(
        "mma.sync.aligned.m16n8k16.row.col.f32.bf16.bf16.f32 "
        "{%0,%1,%2,%3}, {%4,%5,%6,%7}, {%8,%9}, {%0,%1,%2,%3};"
        : "+f"(c[0]), "+f"(c[1]), "+f"(c[2]), "+f"(c[3])
        : "r"(a.x), "r"(a.y), "r"(a.z), "r"(a.w), "r"(b0), "r"(b1));
}

template <int MODE>
__global__ __launch_bounds__(128, 8) void tcgemm(
    const float* __restrict__ A1, int sA1, int K1,
    const float* __restrict__ A2, int sA2, int K2,
    const unsigned* __restrict__ Wswz, int k16Stride, int chOff,
    const float* __restrict__ bias,
    int nReal,
    float* __restrict__ cio,
    float* __restrict__ outp, int sOut,
    float* __restrict__ clipOut,
    float* __restrict__ extra)
{
    __shared__ float sbuf[32 * 18];
    const int K = K1 + K2;
    const int nch = K >> 4;
    const int tid = threadIdx.x;
    const int lane = tid & 31, warp = tid >> 5;
    const int wn = warp & 1, wb = warp >> 1;
    const int nblk = blockIdx.x;
    const int b0 = blockIdx.y * 16;

    float acc[4] = {0.f, 0.f, 0.f, 0.f};

    const uint4* Wp = (const uint4*)Wswz
        + ((size_t)(nblk * 2 + wn) * k16Stride + chOff) * 64 + lane;

    const int bcol = b0 + wb * 8 + (lane >> 2);
    const int kb = 2 * (lane & 3);
    const float* rA1 = A1 + (size_t)bcol * sA1;
    const float* rA2 = A2 + (size_t)bcol * sA2 - K1;

    float2 B0[2], B1[2];
    uint4 WH[2], WL[2];

    auto ldB = [&](int ch, float2& v0, float2& v1) {
        int k = ch * 16 + kb;
        const float* s = (k < K1) ? rA1 : rA2;
        v0 = *(const float2*)(s + k);
        v1 = *(const float2*)(s + k + 8);
    };

    ldB(0, B0[0], B1[0]);
    WH[0] = Wp[0];
    WL[0] = Wp[32];
    if (nch > 1) {
        ldB(1, B0[1], B1[1]);
        WH[1] = Wp[64];
        WL[1] = Wp[96];
    }

    for (int ch = 0; ch < nch; ++ch) {
        const int s = ch & 1;
        uint32_t bh0, bl0, bh1, bl1;
        cvt_hilo(B0[s].x, B0[s].y, bh0, bl0);
        cvt_hilo(B1[s].x, B1[s].y, bh1, bl1);
        mma_bf16(acc, WH[s], bh0, bh1);
        mma_bf16(acc, WL[s], bh0, bh1);
        mma_bf16(acc, WH[s], bl0, bl1);
        if (ch + 2 < nch) {
            ldB(ch + 2, B0[s], B1[s]);
            WH[s] = Wp[(size_t)(ch + 2) * 64];
            WL[s] = Wp[(size_t)(ch + 2) * 64 + 32];
        }
    }

    const int CP = 18;
    {
        int r = lane >> 2;
        int cc = 2 * (lane & 3);
        int nl = wn * 16 + r;
        int blc = wb * 8 + cc;
        sbuf[nl * CP + blc] = acc[0];
        sbuf[nl * CP + blc + 1] = acc[1];
        sbuf[(nl + 8) * CP + blc] = acc[2];
        sbuf[(nl + 8) * CP + blc + 1] = acc[3];
    }
    __syncthreads();

    if (MODE == 0) {
        int j = tid & 7, bl = tid >> 3;
        int jg = nblk * 8 + j;
        int b = b0 + bl;
        float e0 = 0.f, e1 = 0.f, e2 = 0.f, e3 = 0.f;
        if (extra) {
            const float* ep = extra + (size_t)(nblk * 32 + j * 4) * NB + b;
            e0 = ep[0]; e1 = ep[NB]; e2 = ep[2 * NB]; e3 = ep[3 * NB];
        }
        float gi = sbuf[(j * 4 + 0) * CP + bl] + bias[nblk * 32 + j * 4 + 0] + e0;
        float gf = sbuf[(j * 4 + 1) * CP + bl] + bias[nblk * 32 + j * 4 + 1] + e1;
        float gg = sbuf[(j * 4 + 2) * CP + bl] + bias[nblk * 32 + j * 4 + 2] + e2;
        float go = sbuf[(j * 4 + 3) * CP + bl] + bias[nblk * 32 + j * 4 + 3] + e3;
        float cold = cio[(size_t)b * NH + jg];
        float cn = sigf(gf) * cold + sigf(gi) * tanhf(gg);
        float hn = sigf(go) * tanhf(cn);
        cio[(size_t)b * NH + jg] = cn;
        outp[(size_t)b * sOut + jg] = hn;
        if (clipOut) clipOut[(size_t)b * NNIN + jg] = clipf(hn);
    } else {
#pragma unroll
        for (int i = 0; i < 4; ++i) {
            int pair = i * 128 + tid;
            int n = pair & 31, bl = pair >> 5;
            int ng = nblk * 32 + n;
            if (ng < nReal) {
                int b = b0 + bl;
                outp[(size_t)b * sOut + ng] = sbuf[n * CP + bl] + bias[ng];
            }
        }
    }
}

// ---------------- fused iface GEMV + DNC memory step -------------------------
// one block per batch row, 512 threads (16 warps).
__global__ __launch_bounds__(512) void memifstep(
    const float* __restrict__ xsrc,   // g_inp: cols 0..511 already clipped
    const float* __restrict__ Wi,     // [NIF][NH] raw fp32
    const float* __restrict__ bi,     // [NIF]
    float* __restrict__ memg, float* __restrict__ linkg,
    float* __restrict__ precg, float* __restrict__ rwg,
    float* __restrict__ wwg, float* __restrict__ usg,
    float* __restrict__ inp)
{
    const int RS = 80, WK = 84, WS = 104, ER = 105, WV = 125,
              FG = 145, AG = 149, WG = 150, RM = 151;
    const int b = blockIdx.x;
    const int tid = threadIdx.x;
    const int warp = tid >> 5, lane = tid & 31;

    __shared__ __align__(16) float xs[NH];
    __shared__ float ifc[NIF + 1];
    __shared__ float sm[NM * NWC];
    __shared__ float sl[NM * NM];
    __shared__ float sp[NM], srw[NR * NM], sww[NM], sus[NM];
    __shared__ float wcw[NM], alo[NM];
    __shared__ float rcw[NR * NM], fwd[NR * NM], bwd[NR * NM];

    if (tid < NH / 4)
        ((float4*)xs)[tid] = ((const float4*)(xsrc + (size_t)b * NNIN))[tid];
    for (int i = tid; i < NM * NWC; i += 512) sm[i] = memg[b * NM * NWC + i];
    for (int i = tid; i < NM * NM; i += 512) sl[i] = linkg[b * NM * NM + i];
    if (tid < NM) {
        sp[tid] = precg[b * NM + tid];
        sww[tid] = wwg[b * NM + tid];
        sus[tid] = usg[b * NM + tid];
    }
    if (tid >= 32 && tid < 32 + NR * NM) srw[tid - 32] = rwg[b * NR * NM + tid - 32];
    __syncthreads();

    // iface = Wi @ xs + bi : warp-per-row, rows r = warp + 16k
    const float4* xs4 = (const float4*)xs;
    for (int r = warp; r < NIF; r += 16) {
        const float4* wr = (const float4*)(Wi + (size_t)r * NH);
        float4 w0 = wr[lane];
        float4 w1 = wr[lane + 32];
        float4 w2 = wr[lane + 64];
        float4 w3 = wr[lane + 96];
        float4 x0 = xs4[lane];
        float4 x1 = xs4[lane + 32];
        float4 x2 = xs4[lane + 64];
        float4 x3 = xs4[lane + 96];
        float s0 = fmaf(w0.x, x0.x, fmaf(w0.y, x0.y, fmaf(w0.z, x0.z, w0.w * x0.w)));
        float s1 = fmaf(w1.x, x1.x, fmaf(w1.y, x1.y, fmaf(w1.z, x1.z, w1.w * x1.w)));
        float s2 = fmaf(w2.x, x2.x, fmaf(w2.y, x2.y, fmaf(w2.z, x2.z, w2.w * x2.w)));
        float s3 = fmaf(w3.x, x3.x, fmaf(w3.y, x3.y, fmaf(w3.z, x3.z, w3.w * x3.w)));
        float s = (s0 + s1) + (s2 + s3);
#pragma unroll
        for (int o = 16; o > 0; o >>= 1) s += __shfl_down_sync(0xffffffffu, s, o);
        if (lane == 0) ifc[r] = s + bi[r];
    }
    __syncthreads();

    // usage update (OLD ww, OLD rw)
    if (tid < NM) {
        int m = tid;
        float uu = sus[m] + (1.f - sus[m]) * sww[m];
        float psi = 1.f;
#pragma unroll
        for (int r = 0; r < NR; ++r)
            psi *= 1.f - sigf(ifc[FG + r]) * srw[r * NM + m];
        sus[m] = uu * psi;
    }
    __syncthreads();

    // write content weights (cosine on OLD memory)
    if (tid < NM) {
        int m = tid;
        float kn2 = 0.f, dot = 0.f, mn2 = 0.f;
#pragma unroll
        for (int w = 0; w < NWC; ++w) {
            float kv = tanhf(ifc[WK + w]);
            float mv = sm[m * NWC + w];
            kn2 = fmaf(kv, kv, kn2);
            mn2 = fmaf(mv, mv, mn2);
            dot = fmaf(kv, mv, dot);
        }
        wcw[m] = dot / ((sqrtf(kn2) + EPSF) * (sqrtf(mn2) + EPSF));
    }
    __syncthreads();
    if (tid == 0) {
        float str = softplusf(ifc[WS]);
        float mx = -1e30f;
        for (int m = 0; m < NM; ++m) { wcw[m] *= str; mx = fmaxf(mx, wcw[m]); }
        float s = 0.f;
        for (int m = 0; m < NM; ++m) { wcw[m] = expf(wcw[m] - mx); s += wcw[m]; }
        float inv = 1.f / s;
        for (int m = 0; m < NM; ++m) wcw[m] *= inv;
    }
    // allocation weights (stable ascending argsort of u)
    if (tid == 32) {
        float u[NM]; int idx[NM];
        for (int m = 0; m < NM; ++m) { u[m] = DELTAF + (1.f - DELTAF) * sus[m]; idx[m] = m; }
        for (int i = 1; i < NM; ++i) {
            float kv = u[i]; int ki = idx[i]; int j = i;
            while (j > 0 && u[j - 1] > kv) { u[j] = u[j - 1]; idx[j] = idx[j - 1]; --j; }
            u[j] = kv; idx[j] = ki;
        }
        float prod = 1.f;
        for (int j = 0; j < NM; ++j) { alo[idx[j]] = (1.f - u[j]) * prod; prod *= u[j]; }
    }
    __syncthreads();

    // new write weights
    if (tid < NM) {
        float ag = sigf(ifc[AG]), wg = sigf(ifc[WG]);
        sww[tid] = wg * (ag * alo[tid] + (1.f - ag) * wcw[tid]);
    }
    __syncthreads();

    // memory write
    for (int i = tid; i < NM * NWC; i += 512) {
        int m = i / NWC, w = i % NWC;
        float e = sigf(ifc[ER + w]);
        float v = tanhf(ifc[WV + w]);
        sm[i] = sm[i] * (1.f - sww[m] * e) + sww[m] * v;
    }
    __syncthreads();

    // link update (NEW ww, OLD prec)
    for (int i = tid; i < NM * NM; i += 512) {
        int ii = i >> 4, jj = i & 15;
        sl[i] = (ii == jj) ? 0.f
                           : (1.f - sww[ii] - sww[jj]) * sl[i] + sww[ii] * sp[jj];
    }
    __syncthreads();

    // precedence
    if (tid < NM) {
        float s = 0.f;
#pragma unroll
        for (int m = 0; m < NM; ++m) s += sww[m];
        sp[tid] = (1.f - s) * sp[tid] + sww[tid];
    }
    __syncthreads();

    // read content weights (cosine on NEW memory)
    if (tid < NR * NM) {
        int r = tid >> 4, m = tid & 15;
        float kn2 = 0.f, dot = 0.f, mn2 = 0.f;
#pragma unroll
        for (int w = 0; w < NWC; ++w) {
            float kv = tanhf(ifc[r * NWC + w]);
            float mv = sm[m * NWC + w];
            kn2 = fmaf(kv, kv, kn2);
            mn2 = fmaf(mv, mv, mn2);
            dot = fmaf(kv, mv, dot);
        }
        rcw[tid] = dot / ((sqrtf(kn2) + EPSF) * (sqrtf(mn2) + EPSF));
    }
    __syncthreads();
    if (tid < NR) {
        int r = tid;
        float str = softplusf(ifc[RS + r]);
        float mx = -1e30f;
        for (int m = 0; m < NM; ++m) { rcw[r * NM + m] *= str; mx = fmaxf(mx, rcw[r * NM + m]); }
        float s = 0.f;
        for (int m = 0; m < NM; ++m) { rcw[r * NM + m] = expf(rcw[r * NM + m] - mx); s += rcw[r * NM + m]; }
        float inv = 1.f / s;
        for (int m = 0; m < NM; ++m) rcw[r * NM + m] *= inv;
    }
    __syncthreads();

    // forward / backward (NEW link, OLD rw)
    if (tid < NR * NM) {
        int r = tid >> 4, q = tid & 15;
        float f = 0.f, bb = 0.f;
#pragma unroll
        for (int j = 0; j < NM; ++j) {
            f = fmaf(sl[q * NM + j], srw[r * NM + j], f);
            bb = fmaf(srw[r * NM + j], sl[j * NM + q], bb);
        }
        fwd[tid] = f;
        bwd[tid] = bb;
    }
    __syncthreads();

    // new read weights (mode softmax over 3)
    if (tid < NR * NM) {
        int r = tid >> 4;
        float e0 = ifc[RM + r * 3 + 0], e1 = ifc[RM + r * 3 + 1], e2 = ifc[RM + r * 3 + 2];
        float mx = fmaxf(e0, fmaxf(e1, e2));
        float x0 = expf(e0 - mx), x1 = expf(e1 - mx), x2 = expf(e2 - mx);
        float inv = 1.f / (x0 + x1 + x2);
        srw[tid] = (x0 * bwd[tid] + x1 * fwd[tid] + x2 * rcw[tid]) * inv;
    }
    __syncthreads();

    // read vectors -> g_inp[:, 512:592]
    if (tid < NRW) {
        int r = tid / NWC, w = tid % NWC;
        float s = 0.f;
#pragma unroll
        for (int m = 0; m < NM; ++m) s = fmaf(srw[r * NM + m], sm[m * NWC + w], s);
        inp[(size_t)b * NNIN + NIN + tid] = s;
    }

    // write back state
    for (int i = tid; i < NM * NWC; i += 512) memg[b * NM * NWC + i] = sm[i];
    for (int i = tid; i < NM * NM; i += 512) linkg[b * NM * NM + i] = sl[i];
    if (tid < NM) {
        precg[b * NM + tid] = sp[tid];
        wwg[b * NM + tid] = sww[tid];
        usg[b * NM + tid] = sus[tid];
    }
    if (tid >= 32 && tid < 32 + NR * NM) rwg[b * NR * NM + tid - 32] = srw[tid - 32];
}

// ---------------- x-precompute (one-time; R11-proven, 4x W reuse) -------------
__global__ __launch_bounds__(128) void xprep(
    const float* __restrict__ x, const unsigned* __restrict__ W,
    float* __restrict__ xpart)
{
    __shared__ float sbuf[4][16 * 9];
    const int lane = threadIdx.x & 31, warp = threadIdx.x >> 5;
    const int job = blockIdx.x * 4 + warp;        // 0..16383
    const int nfrag = job & 127;                  // n' 16-row frag
    const int tq = job >> 7;                      // rows tq*32..+31 of b*NT+t
    const uint4* Wp = (const uint4*)W + (size_t)nfrag * 64 * 64 + lane;
    const int kb = 2 * (lane & 3);
    const float* rA[4];
#pragma unroll
    for (int f = 0; f < 4; ++f)
        rA[f] = x + (size_t)(tq * 32 + f * 8 + (lane >> 2)) * NIN;
    float acc[4][4];
#pragma unroll
    for (int f = 0; f < 4; ++f)
        acc[f][0] = acc[f][1] = acc[f][2] = acc[f][3] = 0.f;
    for (int ch = 0; ch < 32; ++ch) {
        uint4 WH = Wp[(size_t)ch * 64];
        uint4 WL = Wp[(size_t)ch * 64 + 32];
        int k = ch * 16 + kb;
#pragma unroll
        for (int f = 0; f < 4; ++f) {
            float2 v0 = *(const float2*)(rA[f] + k);
            float2 v1 = *(const float2*)(rA[f] + k + 8);
            uint32_t bh0, bl0, bh1, bl1;
            cvt_hilo(v0.x, v0.y, bh0, bl0);
            cvt_hilo(v1.x, v1.y, bh1, bl1);
            mma_bf16(acc[f], WH, bh0, bh1);
            mma_bf16(acc[f], WL, bh0, bh1);
            mma_bf16(acc[f], WH, bl0, bl1);
        }
    }
    float* slab = sbuf[warp];
    int r = lane >> 2, cc = 2 * (lane & 3);
#pragma unroll
    for (int f = 0; f < 4; ++f) {
        __syncwarp();
        slab[r * 9 + cc] = acc[f][0];
        slab[r * 9 + cc + 1] = acc[f][1];
        slab[(r + 8) * 9 + cc] = acc[f][2];
        slab[(r + 8) * 9 + cc + 1] = acc[f][3];
        __syncwarp();
#pragma unroll
        for (int i = 0; i < 4; ++i) {
            int idx = i * 32 + lane;
            int n = idx >> 3, bl = idx & 7;
            int ng = nfrag * 16 + n;
            int bg = tq * 32 + f * 8 + bl;        // = b*NT + t
            int t = bg & (NT - 1);
            int bi = bg >> 5;
            xpart[((size_t)t * 2048 + ng) * NB + bi] = slab[n * 9 + bl];
        }
    }
}

// ---------------- host driver ------------------------------------------------
extern "C" void kernel_launch(void* const* d_in, const int* in_sizes, int n_in,
                              void* d_out, int out_size)
{
    const float* x      = (const float*)d_in[0];
    const float* W_ih0  = (const float*)d_in[1];
    const float* W_hh0  = (const float*)d_in[2];
    const float* b_ih0  = (const float*)d_in[3];
    const float* b_hh0  = (const float*)d_in[4];
    const float* W_ih1  = (const float*)d_in[5];
    const float* W_hh1  = (const float*)d_in[6];
    const float* b_ih1  = (const float*)d_in[7];
    const float* b_hh1  = (const float*)d_in[8];
    const float* W_if   = (const float*)d_in[9];
    const float* b_if   = (const float*)d_in[10];
    const float* W_out  = (const float*)d_in[11];
    const float* b_out  = (const float*)d_in[12];
    float* y = (float*)d_out;

    float *ph, *pc, *pinp, *pxp, *pmem, *plink, *pprec, *prw, *pww, *pus, *pbc;
    unsigned *pW00, *pW01, *pW10, *pW11, *pWo;
    cudaGetSymbolAddress((void**)&ph,   g_h);
    cudaGetSymbolAddress((void**)&pc,   g_c);
    cudaGetSymbolAddress((void**)&pinp, g_inp);
    cudaGetSymbolAddress((void**)&pxp,  g_xpart);
    cudaGetSymbolAddress((void**)&pmem, g_mem);
    cudaGetSymbolAddress((void**)&plink,g_link);
    cudaGetSymbolAddress((void**)&pprec,g_prec);
    cudaGetSymbolAddress((void**)&prw,  g_rw);
    cudaGetSymbolAddress((void**)&pww,  g_ww);
    cudaGetSymbolAddress((void**)&pus,  g_usage);
    cudaGetSymbolAddress((void**)&pW00, g_W00);
    cudaGetSymbolAddress((void**)&pW01, g_W01);
    cudaGetSymbolAddress((void**)&pW10, g_W10);
    cudaGetSymbolAddress((void**)&pW11, g_W11);
    cudaGetSymbolAddress((void**)&pWo,  g_Wo);
    cudaGetSymbolAddress((void**)&pbc,  g_bc);

    auto hbuf = [&](int p, int l, int s) {
        return ph + (((size_t)p * 2 + l) * 2 + s) * NB * NH;
    };
    auto cbuf = [&](int l, int s) { return pc + ((size_t)l * 2 + s) * NB * NH; };

    initk<<<512, 256>>>();
    prepAll<<<dim3(1104, 5), 256>>>(W_ih0, W_hh0, W_ih1, W_hh1, W_out,
                                    pW00, pW01, pW10, pW11, pWo);
    prepbias<<<(2 * 2 * 2048 + 255) / 256, 256>>>(b_ih0, b_hh0, b_ih1, b_hh1, pbc);
    xprep<<<4096, 128>>>(x, pW00, pxp);

    const unsigned* Wc1[2] = {pW10, pW11};
    const dim3 gCell(64, 8);
    const dim3 gOut(16, 8);

    for (int t = 0; t < NT; ++t) {
        const int p = t & 1;
        for (int l = 0; l < 2; ++l) {
            // ---- cell 0 ----
            if (l == 0) {
                tcgemm<0><<<gCell, 128>>>(
                    hbuf(p, 0, 0), NH, 512, hbuf(p, 0, 0), NH, 0,
                    pW00, 64, 32,
                    pbc, 2048,
                    cbuf(0, 0),
                    hbuf(p ^ 1, 0, 0), NH,
                    nullptr,
                    pxp + (size_t)t * 2048 * NB);
            } else {
                tcgemm<0><<<gCell, 128>>>(
                    pinp, NNIN, 592, hbuf(p, 1, 0), NH, 512,
                    pW01, 69, 0,
                    pbc + (size_t)2 * 2048, 2048,
                    cbuf(1, 0),
                    hbuf(p ^ 1, 1, 0), NH,
                    nullptr, nullptr);
            }
            // ---- cell 1 ----
            tcgemm<0><<<gCell, 128>>>(
                hbuf(p ^ 1, l, 0), NH, 512, hbuf(p, l, 1), NH, 512,
                Wc1[l], 64, 0,
                pbc + (size_t)(l * 2 + 1) * 2048, 2048,
                cbuf(l, 1),
                hbuf(p ^ 1, l, 1), NH,
                pinp, nullptr);
            // ---- fused iface + memory step ----
            memifstep<<<NB, 512>>>(
                pinp,
                W_if + (size_t)l * NIF * NH, b_if + (size_t)l * NIF,
                pmem + (size_t)l * NB * NM * NWC,
                plink + (size_t)l * NB * NM * NM,
                pprec + (size_t)l * NB * NM,
                prw + (size_t)l * NB * NR * NM,
                pww + (size_t)l * NB * NM,
                pus + (size_t)l * NB * NM,
                pinp);
        }
        // ---- output projection ----
        tcgemm<1><<<gOut, 128>>>(
            pinp, NNIN, 592, pinp, NNIN, 0,
            pWo, 37, 0,
            b_out, 512,
            nullptr, y + (size_t)t * NIN, NT * NIN, nullptr, nullptr);
    }
}

// round 16
// speedup vs baseline: 1.4428x; 1.1641x over previous
#include <cuda_runtime.h>
#include <cuda_bf16.h>
#include <math.h>
#include <stdint.h>

#define NB 128
#define NT 32
#define NIN 512
#define NH 512
#define NM 16
#define NWC 20
#define NR 4
#define NRW 80
#define NNIN 592
#define NIF 163
#define CLIPV 20.0f
#define EPSF 1e-6f
#define DELTAF 5e-6f

// ---------------- persistent state (device globals; allocation-free) ----------
__device__ float g_h[2][2][2][NB][NH];   // [parity][layer][cell][b][h]
__device__ float g_c[2][2][NB][NH];      // [layer][cell][b][h]
__device__ float g_inp[NB][NNIN];        // concat(out, read_vecs)
__device__ float g_xpart[NT * 2048 * NB];// precomputed x@Wih partial, [t][n'][b]
__device__ float g_mem[2][NB][NM][NWC];
__device__ float g_link[2][NB][NM][NM];
__device__ float g_prec[2][NB][NM];
__device__ float g_rw[2][NB][NR][NM];
__device__ float g_ww[2][NB][NM];
__device__ float g_usage[2][NB][NM];

// ---------------- converted (bf16 hi/lo split, fragment-swizzled) weights ----
// layout: [nfrag][k16][hl 2][lane 32][4 u32]
__device__ unsigned g_W00[128 * 64 * 256];   // l0 cell0: 2048 x (512x + 512h)
__device__ unsigned g_W01[128 * 69 * 256];   // l1 cell0: 2048 x 1104
__device__ unsigned g_W10[128 * 64 * 256];   // l0 cell1
__device__ unsigned g_W11[128 * 64 * 256];   // l1 cell1
__device__ unsigned g_Wo[32 * 37 * 256];     // out: 512 x 592
__device__ float g_bc[2 * 2 * 2048];         // gate-reordered biases [l][cell][n']

__device__ __forceinline__ float sigf(float x) { return 1.f / (1.f + expf(-x)); }
__device__ __forceinline__ float softplusf(float x) {
    return fmaxf(x, 0.f) + log1pf(expf(-fabsf(x)));
}
__device__ __forceinline__ float clipf(float x) {
    return fminf(fmaxf(x, -CLIPV), CLIPV);
}
__device__ __forceinline__ uint32_t packbf(float a, float b) {
    uint32_t r;
    asm("cvt.rn.bf16x2.f32 %0, %1, %2;" : "=r"(r) : "f"(b), "f"(a));
    return r;
}
__device__ __forceinline__ float bfhi(float x) {
    return __bfloat162float(__float2bfloat16_rn(x));
}
__device__ __forceinline__ void cvt_hilo(float x, float y, uint32_t& hi, uint32_t& lo) {
    uint32_t h = packbf(x, y);
    float hx = __uint_as_float(h << 16);
    float hy = __uint_as_float(h & 0xffff0000u);
    lo = packbf(x - hx, y - hy);
    hi = h;
}

// ---------------- init: zero all state --------------------------------------
__global__ void initk() {
    long i0 = blockIdx.x * (long)blockDim.x + threadIdx.x;
    long st = (long)gridDim.x * blockDim.x;
    for (long i = i0; i < 2L * 2 * 2 * NB * NH; i += st) ((float*)g_h)[i] = 0.f;
    for (long i = i0; i < 2L * 2 * NB * NH; i += st) ((float*)g_c)[i] = 0.f;
    for (long i = i0; i < (long)NB * NNIN; i += st) ((float*)g_inp)[i] = 0.f;
    for (long i = i0; i < 2L * NB * NM * NWC; i += st) ((float*)g_mem)[i] = 0.f;
    for (long i = i0; i < 2L * NB * NM * NM; i += st) ((float*)g_link)[i] = 0.f;
    for (long i = i0; i < 2L * NB * NM; i += st) {
        ((float*)g_prec)[i] = 0.f;
        ((float*)g_ww)[i] = 0.f;
        ((float*)g_usage)[i] = 0.f;
    }
    for (long i = i0; i < 2L * NB * NR * NM; i += st) ((float*)g_rw)[i] = 0.f;
}

// ---------------- fused weight conversion pre-pass (5 jobs, bf16 hi/lo) ------
__global__ void prepAll(
    const float* __restrict__ W_ih0, const float* __restrict__ W_hh0,
    const float* __restrict__ W_ih1, const float* __restrict__ W_hh1,
    const float* __restrict__ W_out,
    unsigned* pW00, unsigned* pW01, unsigned* pW10, unsigned* pW11,
    unsigned* pWo)
{
    const float *W1, *W2;
    int ld1, K1, ld2, K2, gr, nReal, nPad;
    unsigned* dst;
    switch (blockIdx.y) {
        case 0: W1 = W_ih0; ld1 = NNIN; K1 = 512; W2 = W_hh0; ld2 = NH; K2 = 512;
                dst = pW00; gr = 1; nReal = 2048; nPad = 2048; break;
        case 1: W1 = W_ih0 + (size_t)4 * NH * NNIN; ld1 = NNIN; K1 = 592;
                W2 = W_hh0 + (size_t)4 * NH * NH; ld2 = NH; K2 = 512;
                dst = pW01; gr = 1; nReal = 2048; nPad = 2048; break;
        case 2: W1 = W_ih1; ld1 = NH; K1 = 512; W2 = W_hh1; ld2 = NH; K2 = 512;
                dst = pW10; gr = 1; nReal = 2048; nPad = 2048; break;
        case 3: W1 = W_ih1 + (size_t)4 * NH * NH; ld1 = NH; K1 = 512;
                W2 = W_hh1 + (size_t)4 * NH * NH; ld2 = NH; K2 = 512;
                dst = pW11; gr = 1; nReal = 2048; nPad = 2048; break;
        default: W1 = W_out; ld1 = NNIN; K1 = 592; W2 = W_out; ld2 = NNIN; K2 = 0;
                dst = pWo; gr = 0; nReal = 512; nPad = 512; break;
    }
    const int K16 = (K1 + K2) >> 4;
    int idx = blockIdx.x * blockDim.x + threadIdx.x;
    int total = (nPad >> 4) * K16 * 32;
    if (idx >= total) return;
    int lane = idx & 31;
    int k16 = (idx >> 5) % K16;
    int nfrag = (idx >> 5) / K16;
    int r0 = lane >> 2, c0 = lane & 3;
    uint4 hi, lo;
    unsigned* ph = (unsigned*)&hi;
    unsigned* pl = (unsigned*)&lo;
#pragma unroll
    for (int reg = 0; reg < 4; ++reg) {
        int r = nfrag * 16 + r0 + 8 * (reg & 1);
        int kb = k16 * 16 + 2 * c0 + 8 * (reg >> 1);
        int row;
        if (gr) { int j = r >> 2, g = r & 3; row = g * NH + j; }
        else row = r;
        float x0 = 0.f, x1 = 0.f;
        if (row < nReal) {
            x0 = (kb < K1) ? W1[(size_t)row * ld1 + kb]
                           : W2[(size_t)row * ld2 + (kb - K1)];
            x1 = (kb + 1 < K1) ? W1[(size_t)row * ld1 + kb + 1]
                               : W2[(size_t)row * ld2 + (kb + 1 - K1)];
        }
        float h0 = bfhi(x0), h1 = bfhi(x1);
        ph[reg] = packbf(h0, h1);
        pl[reg] = packbf(x0 - h0, x1 - h1);
    }
    ((uint4*)dst)[((size_t)(nfrag * K16 + k16) * 2 + 0) * 32 + lane] = hi;
    ((uint4*)dst)[((size_t)(nfrag * K16 + k16) * 2 + 1) * 32 + lane] = lo;
}

__global__ void prepbias(const float* bih0, const float* bhh0,
                         const float* bih1, const float* bhh1, float* bc)
{
    int i = blockIdx.x * blockDim.x + threadIdx.x;
    if (i >= 2 * 2 * 2048) return;
    int n = i & 2047;
    int cell = (i >> 11) & 1;
    int l = i >> 12;
    int j = n >> 2, g = n & 3;
    const float* bi = cell ? bih1 : bih0;
    const float* bh = cell ? bhh1 : bhh0;
    bc[i] = bi[(size_t)l * 4 * NH + g * NH + j] + bh[(size_t)l * 4 * NH + g * NH + j];
}

// ---------------- compensated bf16 MMA core ----------------------------------
__device__ __forceinline__ void mma_bf16(float c[4], uint4 a, uint32_t b0, uint32_t b1) {
    asm volatile(
        "mma.sync.aligned.m16n8k16.row.col.f32.bf16.bf16.f32 "
        "{%0,%1,%2,%3}, {%4,%5,%6,%7}, {%8,%9}, {%0,%1,%2,%3};"
        : "+f"(c[0]), "+f"(c[1]), "+f"(c[2]), "+f"(c[3])
        : "r"(a.x), "r"(a.y), "r"(a.z), "r"(a.w), "r"(b0), "r"(b1));
}

// warp GEMM: 16 n' x 16 batch (two 8-batch fragments share each W load)
__device__ __forceinline__ void gemm2(
    const float* __restrict__ A1, int sA1, int K1,
    const float* __restrict__ A2, int sA2,
    int nch, const uint4* __restrict__ Wp,
    int lane, int bc0, float accA[4], float accB[4])
{
    const int kb = 2 * (lane & 3);
    const float* a1A = A1 + (size_t)bc0 * sA1;
    const float* a2A = A2 + (size_t)bc0 * sA2 - K1;
    const float* a1B = A1 + (size_t)(bc0 + 16) * sA1;
    const float* a2B = A2 + (size_t)(bc0 + 16) * sA2 - K1;
    accA[0] = accA[1] = accA[2] = accA[3] = 0.f;
    accB[0] = accB[1] = accB[2] = accB[3] = 0.f;
    float2 BA0[2], BA1[2], BB0[2], BB1[2];
    uint4 WH[2], WL[2];

    auto ld = [&](int ch, int s) {
        int k = ch * 16 + kb;
        const float* pa = (k < K1) ? a1A : a2A;
        const float* pb = (k < K1) ? a1B : a2B;
        BA0[s] = *(const float2*)(pa + k);
        BA1[s] = *(const float2*)(pa + k + 8);
        BB0[s] = *(const float2*)(pb + k);
        BB1[s] = *(const float2*)(pb + k + 8);
    };

    ld(0, 0);
    WH[0] = Wp[0];
    WL[0] = Wp[32];
    if (nch > 1) {
        ld(1, 1);
        WH[1] = Wp[64];
        WL[1] = Wp[96];
    }
    for (int ch = 0; ch < nch; ++ch) {
        const int s = ch & 1;
        uint32_t ah0, al0, ah1, al1, bh0, bl0, bh1, bl1;
        cvt_hilo(BA0[s].x, BA0[s].y, ah0, al0);
        cvt_hilo(BA1[s].x, BA1[s].y, ah1, al1);
        cvt_hilo(BB0[s].x, BB0[s].y, bh0, bl0);
        cvt_hilo(BB1[s].x, BB1[s].y, bh1, bl1);
        mma_bf16(accA, WH[s], ah0, ah1);
        mma_bf16(accA, WL[s], ah0, ah1);
        mma_bf16(accA, WH[s], al0, al1);
        mma_bf16(accB, WH[s], bh0, bh1);
        mma_bf16(accB, WL[s], bh0, bh1);
        mma_bf16(accB, WH[s], bl0, bl1);
        if (ch + 2 < nch) {
            ld(ch + 2, s);
            WH[s] = Wp[(size_t)(ch + 2) * 64];
            WL[s] = Wp[(size_t)(ch + 2) * 64 + 32];
        }
    }
}

// ---------------- step kernel: cell tile (nblk<64) or linear/out tile --------
// MODE 0: cell LSTM (+ appended outproj blocks when grid.x > 64)
// MODE 1: out-projection only (grid.x = 16)
template <int MODE>
__global__ __launch_bounds__(128, 4) void stepk(
    const float* __restrict__ A1, int sA1, int K1,
    const float* __restrict__ A2, int sA2, int K2,
    const unsigned* __restrict__ Wswz, int kstr, int chOff,
    const float* __restrict__ bias,
    float* __restrict__ cio,
    float* __restrict__ outp, int sOut,
    float* __restrict__ clipOut,
    const float* __restrict__ extra,
    const float* __restrict__ oA,
    const unsigned* __restrict__ oW,
    const float* __restrict__ obias,
    float* __restrict__ oy)
{
    __shared__ float sbuf[32 * 34];
    const int CP = 34;
    const int tid = threadIdx.x;
    const int lane = tid & 31, warp = tid >> 5;
    const int wn = warp & 1, wb = warp >> 1;
    const int nblk = blockIdx.x;
    const int b0 = blockIdx.y * 32;
    float accA[4], accB[4];

    if (MODE == 0 && nblk < 64) {
        const int nch = (K1 + K2) >> 4;
        const uint4* Wp = (const uint4*)Wswz
            + ((size_t)(nblk * 2 + wn) * kstr + chOff) * 64 + lane;
        const int bc0 = b0 + wb * 8 + (lane >> 2);
        gemm2(A1, sA1, K1, A2, sA2, nch, Wp, lane, bc0, accA, accB);
        int r = lane >> 2, cc = 2 * (lane & 3);
        int nl = wn * 16 + r, blc = wb * 8 + cc;
        sbuf[nl * CP + blc] = accA[0];
        sbuf[nl * CP + blc + 1] = accA[1];
        sbuf[(nl + 8) * CP + blc] = accA[2];
        sbuf[(nl + 8) * CP + blc + 1] = accA[3];
        sbuf[nl * CP + 16 + blc] = accB[0];
        sbuf[nl * CP + 16 + blc + 1] = accB[1];
        sbuf[(nl + 8) * CP + 16 + blc] = accB[2];
        sbuf[(nl + 8) * CP + 16 + blc + 1] = accB[3];
        __syncthreads();
#pragma unroll
        for (int i = 0; i < 2; ++i) {
            int idx = i * 128 + tid;
            int j = idx & 7, bl = idx >> 3;      // j 0..7, bl 0..31
            int jg = nblk * 8 + j;
            int b = b0 + bl;
            int nb = nblk * 32 + j * 4;
            float e0 = 0.f, e1 = 0.f, e2 = 0.f, e3 = 0.f;
            if (extra) {
                const float* ep = extra + (size_t)nb * NB + b;
                e0 = ep[0]; e1 = ep[NB]; e2 = ep[2 * NB]; e3 = ep[3 * NB];
            }
            float gi = sbuf[(j * 4 + 0) * CP + bl] + bias[nb + 0] + e0;
            float gf = sbuf[(j * 4 + 1) * CP + bl] + bias[nb + 1] + e1;
            float gg = sbuf[(j * 4 + 2) * CP + bl] + bias[nb + 2] + e2;
            float go = sbuf[(j * 4 + 3) * CP + bl] + bias[nb + 3] + e3;
            float cold = cio[(size_t)b * NH + jg];
            float cn = sigf(gf) * cold + sigf(gi) * tanhf(gg);
            float hn = sigf(go) * tanhf(cn);
            cio[(size_t)b * NH + jg] = cn;
            outp[(size_t)b * sOut + jg] = hn;
            if (clipOut) clipOut[(size_t)b * NNIN + jg] = clipf(hn);
        }
    } else {
        const int ob = (MODE == 1) ? nblk : nblk - 64;
        const uint4* Wp = (const uint4*)oW + (size_t)(ob * 2 + wn) * 37 * 64 + lane;
        const int bc0 = b0 + wb * 8 + (lane >> 2);
        gemm2(oA, NNIN, 592, oA, NNIN, 37, Wp, lane, bc0, accA, accB);
        int r = lane >> 2, cc = 2 * (lane & 3);
        int nl = wn * 16 + r, blc = wb * 8 + cc;
        sbuf[nl * CP + blc] = accA[0];
        sbuf[nl * CP + blc + 1] = accA[1];
        sbuf[(nl + 8) * CP + blc] = accA[2];
        sbuf[(nl + 8) * CP + blc + 1] = accA[3];
        sbuf[nl * CP + 16 + blc] = accB[0];
        sbuf[nl * CP + 16 + blc + 1] = accB[1];
        sbuf[(nl + 8) * CP + 16 + blc] = accB[2];
        sbuf[(nl + 8) * CP + 16 + blc + 1] = accB[3];
        __syncthreads();
#pragma unroll
        for (int i = 0; i < 8; ++i) {
            int idx = i * 128 + tid;
            int n = idx & 31, bl = idx >> 5;     // n 0..31, bl 0..31
            int ng = ob * 32 + n;
            int b = b0 + bl;
            oy[(size_t)b * (NT * NIN) + ng] = sbuf[n * CP + bl] + obias[ng];
        }
    }
}

// ---------------- fused iface GEMV + DNC memory step -------------------------
// one block per batch row, 512 threads (16 warps).  (R15-proven)
__global__ __launch_bounds__(512) void memifstep(
    const float* __restrict__ xsrc,   // g_inp: cols 0..511 already clipped
    const float* __restrict__ Wi,     // [NIF][NH] raw fp32
    const float* __restrict__ bi,     // [NIF]
    float* __restrict__ memg, float* __restrict__ linkg,
    float* __restrict__ precg, float* __restrict__ rwg,
    float* __restrict__ wwg, float* __restrict__ usg,
    float* __restrict__ inp)
{
    const int RS = 80, WK = 84, WS = 104, ER = 105, WV = 125,
              FG = 145, AG = 149, WG = 150, RM = 151;
    const int b = blockIdx.x;
    const int tid = threadIdx.x;
    const int warp = tid >> 5, lane = tid & 31;

    __shared__ __align__(16) float xs[NH];
    __shared__ float ifc[NIF + 1];
    __shared__ float sm[NM * NWC];
    __shared__ float sl[NM * NM];
    __shared__ float sp[NM], srw[NR * NM], sww[NM], sus[NM];
    __shared__ float wcw[NM], alo[NM];
    __shared__ float rcw[NR * NM], fwd[NR * NM], bwd[NR * NM];

    if (tid < NH / 4)
        ((float4*)xs)[tid] = ((const float4*)(xsrc + (size_t)b * NNIN))[tid];
    for (int i = tid; i < NM * NWC; i += 512) sm[i] = memg[b * NM * NWC + i];
    for (int i = tid; i < NM * NM; i += 512) sl[i] = linkg[b * NM * NM + i];
    if (tid < NM) {
        sp[tid] = precg[b * NM + tid];
        sww[tid] = wwg[b * NM + tid];
        sus[tid] = usg[b * NM + tid];
    }
    if (tid >= 32 && tid < 32 + NR * NM) srw[tid - 32] = rwg[b * NR * NM + tid - 32];
    __syncthreads();

    const float4* xs4 = (const float4*)xs;
    for (int r = warp; r < NIF; r += 16) {
        const float4* wr = (const float4*)(Wi + (size_t)r * NH);
        float4 w0 = wr[lane];
        float4 w1 = wr[lane + 32];
        float4 w2 = wr[lane + 64];
        float4 w3 = wr[lane + 96];
        float4 x0 = xs4[lane];
        float4 x1 = xs4[lane + 32];
        float4 x2 = xs4[lane + 64];
        float4 x3 = xs4[lane + 96];
        float s0 = fmaf(w0.x, x0.x, fmaf(w0.y, x0.y, fmaf(w0.z, x0.z, w0.w * x0.w)));
        float s1 = fmaf(w1.x, x1.x, fmaf(w1.y, x1.y, fmaf(w1.z, x1.z, w1.w * x1.w)));
        float s2 = fmaf(w2.x, x2.x, fmaf(w2.y, x2.y, fmaf(w2.z, x2.z, w2.w * x2.w)));
        float s3 = fmaf(w3.x, x3.x, fmaf(w3.y, x3.y, fmaf(w3.z, x3.z, w3.w * x3.w)));
        float s = (s0 + s1) + (s2 + s3);
#pragma unroll
        for (int o = 16; o > 0; o >>= 1) s += __shfl_down_sync(0xffffffffu, s, o);
        if (lane == 0) ifc[r] = s + bi[r];
    }
    __syncthreads();

    if (tid < NM) {
        int m = tid;
        float uu = sus[m] + (1.f - sus[m]) * sww[m];
        float psi = 1.f;
#pragma unroll
        for (int r = 0; r < NR; ++r)
            psi *= 1.f - sigf(ifc[FG + r]) * srw[r * NM + m];
        sus[m] = uu * psi;
    }
    __syncthreads();

    if (tid < NM) {
        int m = tid;
        float kn2 = 0.f, dot = 0.f, mn2 = 0.f;
#pragma unroll
        for (int w = 0; w < NWC; ++w) {
            float kv = tanhf(ifc[WK + w]);
            float mv = sm[m * NWC + w];
            kn2 = fmaf(kv, kv, kn2);
            mn2 = fmaf(mv, mv, mn2);
            dot = fmaf(kv, mv, dot);
        }
        wcw[m] = dot / ((sqrtf(kn2) + EPSF) * (sqrtf(mn2) + EPSF));
    }
    __syncthreads();
    if (tid == 0) {
        float str = softplusf(ifc[WS]);
        float mx = -1e30f;
        for (int m = 0; m < NM; ++m) { wcw[m] *= str; mx = fmaxf(mx, wcw[m]); }
        float s = 0.f;
        for (int m = 0; m < NM; ++m) { wcw[m] = expf(wcw[m] - mx); s += wcw[m]; }
        float inv = 1.f / s;
        for (int m = 0; m < NM; ++m) wcw[m] *= inv;
    }
    if (tid == 32) {
        float u[NM]; int idx[NM];
        for (int m = 0; m < NM; ++m) { u[m] = DELTAF + (1.f - DELTAF) * sus[m]; idx[m] = m; }
        for (int i = 1; i < NM; ++i) {
            float kv = u[i]; int ki = idx[i]; int j = i;
            while (j > 0 && u[j - 1] > kv) { u[j] = u[j - 1]; idx[j] = idx[j - 1]; --j; }
            u[j] = kv; idx[j] = ki;
        }
        float prod = 1.f;
        for (int j = 0; j < NM; ++j) { alo[idx[j]] = (1.f - u[j]) * prod; prod *= u[j]; }
    }
    __syncthreads();

    if (tid < NM) {
        float ag = sigf(ifc[AG]), wg = sigf(ifc[WG]);
        sww[tid] = wg * (ag * alo[tid] + (1.f - ag) * wcw[tid]);
    }
    __syncthreads();

    for (int i = tid; i < NM * NWC; i += 512) {
        int m = i / NWC, w = i % NWC;
        float e = sigf(ifc[ER + w]);
        float v = tanhf(ifc[WV + w]);
        sm[i] = sm[i] * (1.f - sww[m] * e) + sww[m] * v;
    }
    __syncthreads();

    for (int i = tid; i < NM * NM; i += 512) {
        int ii = i >> 4, jj = i & 15;
        sl[i] = (ii == jj) ? 0.f
                           : (1.f - sww[ii] - sww[jj]) * sl[i] + sww[ii] * sp[jj];
    }
    __syncthreads();

    if (tid < NM) {
        float s = 0.f;
#pragma unroll
        for (int m = 0; m < NM; ++m) s += sww[m];
        sp[tid] = (1.f - s) * sp[tid] + sww[tid];
    }
    __syncthreads();

    if (tid < NR * NM) {
        int r = tid >> 4, m = tid & 15;
        float kn2 = 0.f, dot = 0.f, mn2 = 0.f;
#pragma unroll
        for (int w = 0; w < NWC; ++w) {
            float kv = tanhf(ifc[r * NWC + w]);
            float mv = sm[m * NWC + w];
            kn2 = fmaf(kv, kv, kn2);
            mn2 = fmaf(mv, mv, mn2);
            dot = fmaf(kv, mv, dot);
        }
        rcw[tid] = dot / ((sqrtf(kn2) + EPSF) * (sqrtf(mn2) + EPSF));
    }
    __syncthreads();
    if (tid < NR) {
        int r = tid;
        float str = softplusf(ifc[RS + r]);
        float mx = -1e30f;
        for (int m = 0; m < NM; ++m) { rcw[r * NM + m] *= str; mx = fmaxf(mx, rcw[r * NM + m]); }
        float s = 0.f;
        for (int m = 0; m < NM; ++m) { rcw[r * NM + m] = expf(rcw[r * NM + m] - mx); s += rcw[r * NM + m]; }
        float inv = 1.f / s;
        for (int m = 0; m < NM; ++m) rcw[r * NM + m] *= inv;
    }
    __syncthreads();

    if (tid < NR * NM) {
        int r = tid >> 4, q = tid & 15;
        float f = 0.f, bb = 0.f;
#pragma unroll
        for (int j = 0; j < NM; ++j) {
            f = fmaf(sl[q * NM + j], srw[r * NM + j], f);
            bb = fmaf(srw[r * NM + j], sl[j * NM + q], bb);
        }
        fwd[tid] = f;
        bwd[tid] = bb;
    }
    __syncthreads();

    if (tid < NR * NM) {
        int r = tid >> 4;
        float e0 = ifc[RM + r * 3 + 0], e1 = ifc[RM + r * 3 + 1], e2 = ifc[RM + r * 3 + 2];
        float mx = fmaxf(e0, fmaxf(e1, e2));
        float x0 = expf(e0 - mx), x1 = expf(e1 - mx), x2 = expf(e2 - mx);
        float inv = 1.f / (x0 + x1 + x2);
        srw[tid] = (x0 * bwd[tid] + x1 * fwd[tid] + x2 * rcw[tid]) * inv;
    }
    __syncthreads();

    if (tid < NRW) {
        int r = tid / NWC, w = tid % NWC;
        float s = 0.f;
#pragma unroll
        for (int m = 0; m < NM; ++m) s = fmaf(srw[r * NM + m], sm[m * NWC + w], s);
        inp[(size_t)b * NNIN + NIN + tid] = s;
    }

    for (int i = tid; i < NM * NWC; i += 512) memg[b * NM * NWC + i] = sm[i];
    for (int i = tid; i < NM * NM; i += 512) linkg[b * NM * NM + i] = sl[i];
    if (tid < NM) {
        precg[b * NM + tid] = sp[tid];
        wwg[b * NM + tid] = sww[tid];
        usg[b * NM + tid] = sus[tid];
    }
    if (tid >= 32 && tid < 32 + NR * NM) rwg[b * NR * NM + tid - 32] = srw[tid - 32];
}

// ---------------- x-precompute (one-time; R11-proven, 4x W reuse) -------------
__global__ __launch_bounds__(128) void xprep(
    const float* __restrict__ x, const unsigned* __restrict__ W,
    float* __restrict__ xpart)
{
    __shared__ float sbuf[4][16 * 9];
    const int lane = threadIdx.x & 31, warp = threadIdx.x >> 5;
    const int job = blockIdx.x * 4 + warp;
    const int nfrag = job & 127;
    const int tq = job >> 7;
    const uint4* Wp = (const uint4*)W + (size_t)nfrag * 64 * 64 + lane;
    const int kb = 2 * (lane & 3);
    const float* rA[4];
#pragma unroll
    for (int f = 0; f < 4; ++f)
        rA[f] = x + (size_t)(tq * 32 + f * 8 + (lane >> 2)) * NIN;
    float acc[4][4];
#pragma unroll
    for (int f = 0; f < 4; ++f)
        acc[f][0] = acc[f][1] = acc[f][2] = acc[f][3] = 0.f;
    for (int ch = 0; ch < 32; ++ch) {
        uint4 WH = Wp[(size_t)ch * 64];
        uint4 WL = Wp[(size_t)ch * 64 + 32];
        int k = ch * 16 + kb;
#pragma unroll
        for (int f = 0; f < 4; ++f) {
            float2 v0 = *(const float2*)(rA[f] + k);
            float2 v1 = *(const float2*)(rA[f] + k + 8);
            uint32_t bh0, bl0, bh1, bl1;
            cvt_hilo(v0.x, v0.y, bh0, bl0);
            cvt_hilo(v1.x, v1.y, bh1, bl1);
            mma_bf16(acc[f], WH, bh0, bh1);
            mma_bf16(acc[f], WL, bh0, bh1);
            mma_bf16(acc[f], WH, bl0, bl1);
        }
    }
    float* slab = sbuf[warp];
    int r = lane >> 2, cc = 2 * (lane & 3);
#pragma unroll
    for (int f = 0; f < 4; ++f) {
        __syncwarp();
        slab[r * 9 + cc] = acc[f][0];
        slab[r * 9 + cc + 1] = acc[f][1];
        slab[(r + 8) * 9 + cc] = acc[f][2];
        slab[(r + 8) * 9 + cc + 1] = acc[f][3];
        __syncwarp();
#pragma unroll
        for (int i = 0; i < 4; ++i) {
            int idx = i * 32 + lane;
            int n = idx >> 3, bl = idx & 7;
            int ng = nfrag * 16 + n;
            int bg = tq * 32 + f * 8 + bl;
            int t = bg & (NT - 1);
            int bi = bg >> 5;
            xpart[((size_t)t * 2048 + ng) * NB + bi] = slab[n * 9 + bl];
        }
    }
}

// ---------------- host driver ------------------------------------------------
extern "C" void kernel_launch(void* const* d_in, const int* in_sizes, int n_in,
                              void* d_out, int out_size)
{
    const float* x      = (const float*)d_in[0];
    const float* W_ih0  = (const float*)d_in[1];
    const float* W_hh0  = (const float*)d_in[2];
    const float* b_ih0  = (const float*)d_in[3];
    const float* b_hh0  = (const float*)d_in[4];
    const float* W_ih1  = (const float*)d_in[5];
    const float* W_hh1  = (const float*)d_in[6];
    const float* b_ih1  = (const float*)d_in[7];
    const float* b_hh1  = (const float*)d_in[8];
    const float* W_if   = (const float*)d_in[9];
    const float* b_if   = (const float*)d_in[10];
    const float* W_out  = (const float*)d_in[11];
    const float* b_out  = (const float*)d_in[12];
    float* y = (float*)d_out;

    float *ph, *pc, *pinp, *pxp, *pmem, *plink, *pprec, *prw, *pww, *pus, *pbc;
    unsigned *pW00, *pW01, *pW10, *pW11, *pWo;
    cudaGetSymbolAddress((void**)&ph,   g_h);
    cudaGetSymbolAddress((void**)&pc,   g_c);
    cudaGetSymbolAddress((void**)&pinp, g_inp);
    cudaGetSymbolAddress((void**)&pxp,  g_xpart);
    cudaGetSymbolAddress((void**)&pmem, g_mem);
    cudaGetSymbolAddress((void**)&plink,g_link);
    cudaGetSymbolAddress((void**)&pprec,g_prec);
    cudaGetSymbolAddress((void**)&prw,  g_rw);
    cudaGetSymbolAddress((void**)&pww,  g_ww);
    cudaGetSymbolAddress((void**)&pus,  g_usage);
    cudaGetSymbolAddress((void**)&pW00, g_W00);
    cudaGetSymbolAddress((void**)&pW01, g_W01);
    cudaGetSymbolAddress((void**)&pW10, g_W10);
    cudaGetSymbolAddress((void**)&pW11, g_W11);
    cudaGetSymbolAddress((void**)&pWo,  g_Wo);
    cudaGetSymbolAddress((void**)&pbc,  g_bc);

    auto hbuf = [&](int p, int l, int s) {
        return ph + (((size_t)p * 2 + l) * 2 + s) * NB * NH;
    };
    auto cbuf = [&](int l, int s) { return pc + ((size_t)l * 2 + s) * NB * NH; };

    initk<<<512, 256>>>();
    prepAll<<<dim3(1104, 5), 256>>>(W_ih0, W_hh0, W_ih1, W_hh1, W_out,
                                    pW00, pW01, pW10, pW11, pWo);
    prepbias<<<(2 * 2 * 2048 + 255) / 256, 256>>>(b_ih0, b_hh0, b_ih1, b_hh1, pbc);
    xprep<<<4096, 128>>>(x, pW00, pxp);

    const unsigned* Wc1[2] = {pW10, pW11};
    const dim3 gCell(64, 4);
    const dim3 gCellO(80, 4);
    const dim3 gOut(16, 4);

    for (int t = 0; t < NT; ++t) {
        const int p = t & 1;
        // ---- cell0-l0 (+ outproj of t-1 on appended blocks) ----
        stepk<0><<<(t == 0 ? gCell : gCellO), 128>>>(
            hbuf(p, 0, 0), NH, 512, hbuf(p, 0, 0), NH, 0,
            pW00, 64, 32,
            pbc,
            cbuf(0, 0),
            hbuf(p ^ 1, 0, 0), NH,
            nullptr,
            pxp + (size_t)t * 2048 * NB,
            pinp, pWo, b_out, (t == 0) ? nullptr : y + (size_t)(t - 1) * NIN);
        // ---- cell1-l0 ----
        stepk<0><<<gCell, 128>>>(
            hbuf(p ^ 1, 0, 0), NH, 512, hbuf(p, 0, 1), NH, 512,
            Wc1[0], 64, 0,
            pbc + (size_t)1 * 2048,
            cbuf(0, 1),
            hbuf(p ^ 1, 0, 1), NH,
            pinp,
            nullptr,
            pinp, pWo, b_out, nullptr);
        // ---- memifstep l0 ----
        memifstep<<<NB, 512>>>(
            pinp,
            W_if, b_if,
            pmem, plink, pprec, prw, pww, pus,
            pinp);
        // ---- cell0-l1 ----
        stepk<0><<<gCell, 128>>>(
            pinp, NNIN, 592, hbuf(p, 1, 0), NH, 512,
            pW01, 69, 0,
            pbc + (size_t)2 * 2048,
            cbuf(1, 0),
            hbuf(p ^ 1, 1, 0), NH,
            nullptr,
            nullptr,
            pinp, pWo, b_out, nullptr);
        // ---- cell1-l1 ----
        stepk<0><<<gCell, 128>>>(
            hbuf(p ^ 1, 1, 0), NH, 512, hbuf(p, 1, 1), NH, 512,
            Wc1[1], 64, 0,
            pbc + (size_t)3 * 2048,
            cbuf(1, 1),
            hbuf(p ^ 1, 1, 1), NH,
            pinp,
            nullptr,
            pinp, pWo, b_out, nullptr);
        // ---- memifstep l1 ----
        memifstep<<<NB, 512>>>(
            pinp,
            W_if + (size_t)NIF * NH, b_if + NIF,
            pmem + (size_t)NB * NM * NWC,
            plink + (size_t)NB * NM * NM,
            pprec + (size_t)NB * NM,
            prw + (size_t)NB * NR * NM,
            pww + (size_t)NB * NM,
            pus + (size_t)NB * NM,
            pinp);
    }
    // ---- final output projection (t = NT-1) ----
    stepk<1><<<gOut, 128>>>(
        pinp, NNIN, 592, pinp, NNIN, 0,
        pWo, 37, 0,
        pbc,
        nullptr, nullptr, 0, nullptr, nullptr,
        pinp, pWo, b_out, y + (size_t)(NT - 1) * NIN);
}